// round 1
// baseline (speedup 1.0000x reference)
#include <cuda_runtime.h>
#include <cstdint>

#define NB 8
#define NC 64
#define NPTS 65536
#define RR 32
#define R3 32768          // 32^3
#define CHUNKS 8
#define CHUNK_N (NPTS / CHUNKS)
#define TILE 128

// ---------------- device scratch (static globals: no runtime allocation) ----------------
__device__ float g_vox[(size_t)NB * R3 * NC];   // voxel SUMS, layout [b][voxel][c] (c contiguous)
__device__ float g_cnt[NB * R3];                // per-voxel point counts
__device__ float g_psum[2][NB][CHUNKS][3];      // partial axis sums  (t: 0=x1,1=x2)
__device__ float g_pmax[2][NB][CHUNKS];         // partial max norms
__device__ float g_mean[2][NB][3];
__device__ float g_scale[2][NB];                // scale = 2 * max ||c - mean||

// ---------------- stats: partial axis sums ----------------
__global__ void k_sum_partial(const float* __restrict__ c1, const float* __restrict__ c2) {
    int blk = blockIdx.x;            // 128 blocks: t(1) | b(3) | chunk(3)
    int t   = blk >> 6;
    int b   = (blk >> 3) & 7;
    int ch  = blk & 7;
    const float* c = (t ? c2 : c1) + (size_t)b * 3 * NPTS + ch * CHUNK_N;

    float sx = 0.f, sy = 0.f, sz = 0.f;
    for (int i = threadIdx.x; i < CHUNK_N; i += 256) {
        sx += c[i];
        sy += c[NPTS + i];
        sz += c[2 * NPTS + i];
    }
    #pragma unroll
    for (int o = 16; o > 0; o >>= 1) {
        sx += __shfl_down_sync(0xffffffffu, sx, o);
        sy += __shfl_down_sync(0xffffffffu, sy, o);
        sz += __shfl_down_sync(0xffffffffu, sz, o);
    }
    __shared__ float rs[8][3];
    if ((threadIdx.x & 31) == 0) {
        int w = threadIdx.x >> 5;
        rs[w][0] = sx; rs[w][1] = sy; rs[w][2] = sz;
    }
    __syncthreads();
    if (threadIdx.x < 3) {
        float s = 0.f;
        #pragma unroll
        for (int w = 0; w < 8; w++) s += rs[w][threadIdx.x];
        g_psum[t][b][ch][threadIdx.x] = s;
    }
}

__global__ void k_mean_final() {
    int i = threadIdx.x;             // 48 items: t*24 + b*3 + ax
    if (i < 48) {
        int t = i / 24, b = (i / 3) % 8, ax = i % 3;
        float s = 0.f;
        #pragma unroll
        for (int ch = 0; ch < CHUNKS; ch++) s += g_psum[t][b][ch][ax];
        g_mean[t][b][ax] = s / (float)NPTS;
    }
}

// ---------------- stats: partial max norm of centered coords ----------------
__global__ void k_max_partial(const float* __restrict__ c1, const float* __restrict__ c2) {
    int blk = blockIdx.x;
    int t   = blk >> 6;
    int b   = (blk >> 3) & 7;
    int ch  = blk & 7;
    const float* c = (t ? c2 : c1) + (size_t)b * 3 * NPTS + ch * CHUNK_N;
    float mx = g_mean[t][b][0], my = g_mean[t][b][1], mz = g_mean[t][b][2];

    float m = 0.f;
    for (int i = threadIdx.x; i < CHUNK_N; i += 256) {
        float dx = c[i] - mx;
        float dy = c[NPTS + i] - my;
        float dz = c[2 * NPTS + i] - mz;
        m = fmaxf(m, sqrtf(dx * dx + dy * dy + dz * dz));
    }
    #pragma unroll
    for (int o = 16; o > 0; o >>= 1)
        m = fmaxf(m, __shfl_down_sync(0xffffffffu, m, o));
    __shared__ float rs[8];
    if ((threadIdx.x & 31) == 0) rs[threadIdx.x >> 5] = m;
    __syncthreads();
    if (threadIdx.x == 0) {
        float mm = 0.f;
        #pragma unroll
        for (int w = 0; w < 8; w++) mm = fmaxf(mm, rs[w]);
        g_pmax[t][b][ch] = mm;
    }
}

__global__ void k_scale_final() {
    int i = threadIdx.x;
    if (i < 16) {
        int t = i >> 3, b = i & 7;
        float m = 0.f;
        #pragma unroll
        for (int ch = 0; ch < CHUNKS; ch++) m = fmaxf(m, g_pmax[t][b][ch]);
        g_scale[t][b] = 2.0f * m;
    }
}

// normalized coordinate in [0, 31]
__device__ __forceinline__ float norm1(float v, float mean, float scale) {
    float x = ((v - mean) / scale + 0.5f) * (float)RR;
    return fminf(fmaxf(x, 0.0f), (float)(RR - 1));
}

// ---------------- voxelize x2 (sums + counts), vec4 global reductions ----------------
__global__ void __launch_bounds__(256) k_voxelize(const float* __restrict__ feat,
                                                  const float* __restrict__ coords) {
    int b  = blockIdx.y;
    int n0 = blockIdx.x * TILE;
    int tid = threadIdx.x;

    __shared__ float sfeat[TILE][68];   // pad 68 -> 16B-aligned rows (272B), moderate STS conflicts
    __shared__ int   sidx[TILE];

    // per-point voxel index (+ count reduction)
    if (tid < TILE) {
        int n = n0 + tid;
        const float* cb = coords + (size_t)b * 3 * NPTS;
        float sc = g_scale[1][b];
        float nx = norm1(cb[n],            g_mean[1][b][0], sc);
        float ny = norm1(cb[NPTS + n],     g_mean[1][b][1], sc);
        float nz = norm1(cb[2 * NPTS + n], g_mean[1][b][2], sc);
        int ix = (int)rintf(nx);
        int iy = (int)rintf(ny);
        int iz = (int)rintf(nz);
        int vi = (ix * RR + iy) * RR + iz;
        sidx[tid] = vi;
        atomicAdd(&g_cnt[b * R3 + vi], 1.0f);
    }

    // coalesced feature load, transposed into smem (point-major)
    {
        int nl = tid & 127;
        for (int c = tid >> 7; c < NC; c += 2)
            sfeat[nl][c] = feat[((size_t)b * NC + c) * NPTS + n0 + nl];
    }
    __syncthreads();

    // scatter: 16 float4 reductions per point
    float* vbase = g_vox + (size_t)b * R3 * NC;
    for (int i = tid; i < TILE * 16; i += 256) {
        int nl = i >> 4;
        int c4 = i & 15;
        float4 v = *(const float4*)&sfeat[nl][c4 * 4];
        float* addr = vbase + (size_t)sidx[nl] * NC + c4 * 4;
        asm volatile("red.global.add.v4.f32 [%0], {%1,%2,%3,%4};"
                     :: "l"(addr), "f"(v.x), "f"(v.y), "f"(v.z), "f"(v.w) : "memory");
    }
}

// ---------------- devoxelize at nc_x1 + concat with x1_features ----------------
__global__ void __launch_bounds__(256) k_devox_concat(const float* __restrict__ x1f,
                                                      const float* __restrict__ x1c,
                                                      float* __restrict__ out) {
    int b  = blockIdx.y;
    int n0 = blockIdx.x * TILE;
    int tid = threadIdx.x;

    __shared__ float sout[TILE][65];    // pad 65 -> conflict-free column reads in phase D
    __shared__ int   sidx[TILE][8];
    __shared__ float sw[TILE][8];

    // Phase A: copy x1_features -> out channels [0,64): float4, fully coalesced
    {
        const float4* src = (const float4*)(x1f + (size_t)b * NC * NPTS);
        float4*       dst = (float4*)(out + (size_t)b * 2 * NC * NPTS);
        int g0 = n0 >> 2;
        for (int i = tid; i < NC * (TILE / 4); i += 256) {
            int c = i >> 5, g = i & 31;
            size_t off = (size_t)c * (NPTS / 4) + g0 + g;
            dst[off] = src[off];
        }
    }

    // Phase B: per-point trilinear corners + weights (count division folded in)
    if (tid < TILE) {
        int n = n0 + tid;
        const float* cb = x1c + (size_t)b * 3 * NPTS;
        float sc = g_scale[0][b];
        float nx = norm1(cb[n],            g_mean[0][b][0], sc);
        float ny = norm1(cb[NPTS + n],     g_mean[0][b][1], sc);
        float nz = norm1(cb[2 * NPTS + n], g_mean[0][b][2], sc);

        float lx = floorf(nx), ly = floorf(ny), lz = floorf(nz);
        float dx = nx - lx,    dy = ny - ly,    dz = nz - lz;
        int ix = (int)lx, iy = (int)ly, iz = (int)lz;
        int hx = min(ix + 1, RR - 1), hy = min(iy + 1, RR - 1), hz = min(iz + 1, RR - 1);

        int   cx[2] = {ix, hx},          cy[2] = {iy, hy},          cz[2] = {iz, hz};
        float wx[2] = {1.f - dx, dx},    wy[2] = {1.f - dy, dy},    wz[2] = {1.f - dz, dz};

        const float* cnt = g_cnt + b * R3;
        #pragma unroll
        for (int k = 0; k < 8; k++) {
            int a = k >> 2, bb = (k >> 1) & 1, cc = k & 1;
            int idx = (cx[a] * RR + cy[bb]) * RR + cz[cc];
            float w = wx[a] * wy[bb] * wz[cc];
            w = w / fmaxf(cnt[idx], 1.0f);        // avg-voxelize division folded into weight
            sidx[tid][k] = idx;
            sw[tid][k]   = w;
        }
    }
    __syncthreads();

    // Phase C: gather-accumulate (coalesced: 16 lanes cover one neighbor's 64 channels)
    {
        const float4* vb = (const float4*)(g_vox + (size_t)b * R3 * NC);
        for (int i = tid; i < TILE * 16; i += 256) {
            int nl = i >> 4;
            int c4 = i & 15;
            float4 acc = make_float4(0.f, 0.f, 0.f, 0.f);
            #pragma unroll
            for (int k = 0; k < 8; k++) {
                int   idx = sidx[nl][k];
                float w   = sw[nl][k];
                float4 v  = vb[(size_t)idx * (NC / 4) + c4];
                acc.x += w * v.x; acc.y += w * v.y; acc.z += w * v.z; acc.w += w * v.w;
            }
            int c = c4 * 4;
            sout[nl][c + 0] = acc.x;
            sout[nl][c + 1] = acc.y;
            sout[nl][c + 2] = acc.z;
            sout[nl][c + 3] = acc.w;
        }
    }
    __syncthreads();

    // Phase D: transpose out of smem -> out channels [64,128), coalesced along N
    {
        float* dsto = out + ((size_t)b * 2 * NC + NC) * NPTS;
        for (int i = tid; i < NC * TILE; i += 256) {
            int c = i >> 7, nl = i & 127;
            dsto[(size_t)c * NPTS + n0 + nl] = sout[nl][c];
        }
    }
}

// ---------------- launch ----------------
extern "C" void kernel_launch(void* const* d_in, const int* in_sizes, int n_in,
                              void* d_out, int out_size) {
    // inputs in reference order: x1_features, x2_features, x1_coords, x2_coords.
    // Defensive: identify features (B*C*N elems) vs coords (B*3*N elems) by size.
    const float* fptr[2] = {nullptr, nullptr};
    const float* cptr[2] = {nullptr, nullptr};
    int fi = 0, ci = 0;
    for (int i = 0; i < 4; i++) {
        if (in_sizes[i] == NB * NC * NPTS) { if (fi < 2) fptr[fi++] = (const float*)d_in[i]; }
        else                               { if (ci < 2) cptr[ci++] = (const float*)d_in[i]; }
    }
    const float* x1f = fptr[0];
    const float* x2f = fptr[1];
    const float* x1c = cptr[0];
    const float* x2c = cptr[1];
    float* out = (float*)d_out;

    void* vox_ptr = nullptr;
    void* cnt_ptr = nullptr;
    cudaGetSymbolAddress(&vox_ptr, g_vox);
    cudaGetSymbolAddress(&cnt_ptr, g_cnt);

    cudaMemsetAsync(vox_ptr, 0, (size_t)NB * R3 * NC * sizeof(float));
    cudaMemsetAsync(cnt_ptr, 0, (size_t)NB * R3 * sizeof(float));

    k_sum_partial<<<2 * NB * CHUNKS, 256>>>(x1c, x2c);
    k_mean_final<<<1, 64>>>();
    k_max_partial<<<2 * NB * CHUNKS, 256>>>(x1c, x2c);
    k_scale_final<<<1, 32>>>();

    dim3 grid(NPTS / TILE, NB);
    k_voxelize<<<grid, 256>>>(x2f, x2c);
    k_devox_concat<<<grid, 256>>>(x1f, x1c, out);
}

// round 2
// speedup vs baseline: 1.1147x; 1.1147x over previous
#include <cuda_runtime.h>
#include <cuda_fp16.h>
#include <cstdint>

#define NB 8
#define NC 64
#define NPTS 65536
#define RR 32
#define R3 32768          // 32^3
#define TILE 128

// ---------------- device scratch ----------------
__device__ float  g_vox [(size_t)NB * R3 * NC];   // voxel SUMS, [b][voxel][c]
__device__ __half g_voxh[(size_t)NB * R3 * NC];   // voxel AVERAGES (fp16), [b][voxel][c]
__device__ float  g_cnt [NB * R3];                // per-voxel point counts
__device__ float  g_mean[2][NB][3];
__device__ float  g_scale[2][NB];                 // 2 * max ||c - mean||

// ---------------- fused stats: mean then max-norm, one block per (t,b) ----------------
__global__ void __launch_bounds__(1024) k_stats(const float* __restrict__ c1,
                                                const float* __restrict__ c2) {
    int t = blockIdx.x >> 3;
    int b = blockIdx.x & 7;
    const float* cb = (t ? c2 : c1) + (size_t)b * 3 * NPTS;
    int tid = threadIdx.x;

    __shared__ float rs[32][3];
    __shared__ float smean[3];

    // pass 1: axis sums
    {
        float sx = 0.f, sy = 0.f, sz = 0.f;
        const float4* px = (const float4*)cb;
        const float4* py = (const float4*)(cb + NPTS);
        const float4* pz = (const float4*)(cb + 2 * NPTS);
        for (int i = tid; i < NPTS / 4; i += 1024) {
            float4 a = px[i]; sx += a.x + a.y + a.z + a.w;
            float4 c = py[i]; sy += c.x + c.y + c.z + c.w;
            float4 e = pz[i]; sz += e.x + e.y + e.z + e.w;
        }
        #pragma unroll
        for (int o = 16; o > 0; o >>= 1) {
            sx += __shfl_down_sync(0xffffffffu, sx, o);
            sy += __shfl_down_sync(0xffffffffu, sy, o);
            sz += __shfl_down_sync(0xffffffffu, sz, o);
        }
        if ((tid & 31) == 0) { int w = tid >> 5; rs[w][0] = sx; rs[w][1] = sy; rs[w][2] = sz; }
        __syncthreads();
        if (tid < 3) {
            float s = 0.f;
            #pragma unroll
            for (int w = 0; w < 32; w++) s += rs[w][tid];
            float m = s / (float)NPTS;
            smean[tid] = m;
            g_mean[t][b][tid] = m;
        }
        __syncthreads();
    }

    // pass 2: max centered norm (re-reads coords; L2-resident)
    {
        float mx = smean[0], my = smean[1], mz = smean[2];
        float mm = 0.f;
        const float4* px = (const float4*)cb;
        const float4* py = (const float4*)(cb + NPTS);
        const float4* pz = (const float4*)(cb + 2 * NPTS);
        for (int i = tid; i < NPTS / 4; i += 1024) {
            float4 a = px[i], c = py[i], e = pz[i];
            float dx, dy, dz;
            dx = a.x - mx; dy = c.x - my; dz = e.x - mz; mm = fmaxf(mm, dx*dx + dy*dy + dz*dz);
            dx = a.y - mx; dy = c.y - my; dz = e.y - mz; mm = fmaxf(mm, dx*dx + dy*dy + dz*dz);
            dx = a.z - mx; dy = c.z - my; dz = e.z - mz; mm = fmaxf(mm, dx*dx + dy*dy + dz*dz);
            dx = a.w - mx; dy = c.w - my; dz = e.w - mz; mm = fmaxf(mm, dx*dx + dy*dy + dz*dz);
        }
        #pragma unroll
        for (int o = 16; o > 0; o >>= 1)
            mm = fmaxf(mm, __shfl_down_sync(0xffffffffu, mm, o));
        if ((tid & 31) == 0) rs[tid >> 5][0] = mm;
        __syncthreads();
        if (tid == 0) {
            float m = 0.f;
            #pragma unroll
            for (int w = 0; w < 32; w++) m = fmaxf(m, rs[w][0]);
            g_scale[t][b] = 2.0f * sqrtf(m);   // norm computed on squared values
        }
    }
}

// normalized coordinate in [0, 31]
__device__ __forceinline__ float norm1(float v, float mean, float scale) {
    float x = ((v - mean) / scale + 0.5f) * (float)RR;
    return fminf(fmaxf(x, 0.0f), (float)(RR - 1));
}

// ---------------- voxelize x2 (sums + counts), vec4 global reductions ----------------
__global__ void __launch_bounds__(256) k_voxelize(const float* __restrict__ feat,
                                                  const float* __restrict__ coords) {
    int b  = blockIdx.y;
    int n0 = blockIdx.x * TILE;
    int tid = threadIdx.x;

    __shared__ float sfeat[TILE][68];
    __shared__ int   sidx[TILE];

    if (tid < TILE) {
        int n = n0 + tid;
        const float* cb = coords + (size_t)b * 3 * NPTS;
        float sc = g_scale[1][b];
        float nx = norm1(cb[n],            g_mean[1][b][0], sc);
        float ny = norm1(cb[NPTS + n],     g_mean[1][b][1], sc);
        float nz = norm1(cb[2 * NPTS + n], g_mean[1][b][2], sc);
        int vi = (((int)rintf(nx)) * RR + (int)rintf(ny)) * RR + (int)rintf(nz);
        sidx[tid] = vi;
        atomicAdd(&g_cnt[b * R3 + vi], 1.0f);
    }

    {
        int nl = tid & 127;
        for (int c = tid >> 7; c < NC; c += 2)
            sfeat[nl][c] = feat[((size_t)b * NC + c) * NPTS + n0 + nl];
    }
    __syncthreads();

    float* vbase = g_vox + (size_t)b * R3 * NC;
    for (int i = tid; i < TILE * 16; i += 256) {
        int nl = i >> 4;
        int c4 = i & 15;
        float4 v = *(const float4*)&sfeat[nl][c4 * 4];
        float* addr = vbase + (size_t)sidx[nl] * NC + c4 * 4;
        asm volatile("red.global.add.v4.f32 [%0], {%1,%2,%3,%4};"
                     :: "l"(addr), "f"(v.x), "f"(v.y), "f"(v.z), "f"(v.w) : "memory");
    }
}

// ---------------- finalize: float sums + counts -> fp16 averages ----------------
__global__ void __launch_bounds__(256) k_finalize() {
    // one thread per (voxel-global, c-octet): 8*32768 voxels * 8 octets = 2.097M threads
    size_t i = (size_t)blockIdx.x * 256 + threadIdx.x;
    size_t vg = i >> 3;                 // global voxel index (b*R3 + v)
    int    c8 = (int)(i & 7);
    float inv = 1.0f / fmaxf(g_cnt[vg], 1.0f);
    const float4* src = (const float4*)(g_vox + vg * NC + c8 * 8);
    float4 a = src[0], c = src[1];
    __half2 h[4];
    h[0] = __floats2half2_rn(a.x * inv, a.y * inv);
    h[1] = __floats2half2_rn(a.z * inv, a.w * inv);
    h[2] = __floats2half2_rn(c.x * inv, c.y * inv);
    h[3] = __floats2half2_rn(c.z * inv, c.w * inv);
    *(uint4*)(g_voxh + vg * NC + c8 * 8) = *(const uint4*)h;
}

// ---------------- devoxelize at nc_x1 + concat with x1_features ----------------
__global__ void __launch_bounds__(256) k_devox_concat(const float* __restrict__ x1f,
                                                      const float* __restrict__ x1c,
                                                      float* __restrict__ out) {
    int b  = blockIdx.y;
    int n0 = blockIdx.x * TILE;
    int tid = threadIdx.x;

    __shared__ float sout[TILE][65];
    __shared__ int   sidx[TILE][8];
    __shared__ float sw[TILE][8];

    // Phase A: copy x1_features -> out channels [0,64)
    {
        const float4* src = (const float4*)(x1f + (size_t)b * NC * NPTS);
        float4*       dst = (float4*)(out + (size_t)b * 2 * NC * NPTS);
        int g0 = n0 >> 2;
        for (int i = tid; i < NC * (TILE / 4); i += 256) {
            int c = i >> 5, g = i & 31;
            size_t off = (size_t)c * (NPTS / 4) + g0 + g;
            dst[off] = src[off];
        }
    }

    // Phase B: trilinear corners + weights (division already folded into grid)
    if (tid < TILE) {
        int n = n0 + tid;
        const float* cb = x1c + (size_t)b * 3 * NPTS;
        float sc = g_scale[0][b];
        float nx = norm1(cb[n],            g_mean[0][b][0], sc);
        float ny = norm1(cb[NPTS + n],     g_mean[0][b][1], sc);
        float nz = norm1(cb[2 * NPTS + n], g_mean[0][b][2], sc);

        float lx = floorf(nx), ly = floorf(ny), lz = floorf(nz);
        float dx = nx - lx,    dy = ny - ly,    dz = nz - lz;
        int ix = (int)lx, iy = (int)ly, iz = (int)lz;
        int hx = min(ix + 1, RR - 1), hy = min(iy + 1, RR - 1), hz = min(iz + 1, RR - 1);

        int   cx[2] = {ix, hx},       cy[2] = {iy, hy},       cz[2] = {iz, hz};
        float wx[2] = {1.f - dx, dx}, wy[2] = {1.f - dy, dy}, wz[2] = {1.f - dz, dz};

        #pragma unroll
        for (int k = 0; k < 8; k++) {
            int a = k >> 2, bb = (k >> 1) & 1, cc = k & 1;
            sidx[tid][k] = (cx[a] * RR + cy[bb]) * RR + cz[cc];
            sw[tid][k]   = wx[a] * wy[bb] * wz[cc];
        }
    }
    __syncthreads();

    // Phase C: fp16 gather-accumulate (8 lanes x 16B cover one corner's 64 channels)
    {
        const uint4* vb = (const uint4*)(g_voxh + (size_t)b * R3 * NC);
        for (int i = tid; i < TILE * 8; i += 256) {
            int nl = i >> 3;
            int c8 = i & 7;
            float acc[8] = {0.f, 0.f, 0.f, 0.f, 0.f, 0.f, 0.f, 0.f};
            #pragma unroll
            for (int k = 0; k < 8; k++) {
                int   idx = sidx[nl][k];
                float w   = sw[nl][k];
                uint4 v = vb[(size_t)idx * (NC / 8) + c8];
                const __half2* hp = (const __half2*)&v;
                #pragma unroll
                for (int j = 0; j < 4; j++) {
                    float2 f = __half22float2(hp[j]);
                    acc[j * 2 + 0] += w * f.x;
                    acc[j * 2 + 1] += w * f.y;
                }
            }
            #pragma unroll
            for (int j = 0; j < 8; j++)
                sout[nl][c8 * 8 + j] = acc[j];
        }
    }
    __syncthreads();

    // Phase D: transpose -> out channels [64,128), coalesced along N
    {
        float* dsto = out + ((size_t)b * 2 * NC + NC) * NPTS;
        for (int i = tid; i < NC * TILE; i += 256) {
            int c = i >> 7, nl = i & 127;
            dsto[(size_t)c * NPTS + n0 + nl] = sout[nl][c];
        }
    }
}

// ---------------- launch ----------------
extern "C" void kernel_launch(void* const* d_in, const int* in_sizes, int n_in,
                              void* d_out, int out_size) {
    const float* fptr[2] = {nullptr, nullptr};
    const float* cptr[2] = {nullptr, nullptr};
    int fi = 0, ci = 0;
    for (int i = 0; i < 4; i++) {
        if (in_sizes[i] == NB * NC * NPTS) { if (fi < 2) fptr[fi++] = (const float*)d_in[i]; }
        else                               { if (ci < 2) cptr[ci++] = (const float*)d_in[i]; }
    }
    const float* x1f = fptr[0];
    const float* x2f = fptr[1];
    const float* x1c = cptr[0];
    const float* x2c = cptr[1];
    float* out = (float*)d_out;

    void* vox_ptr = nullptr;
    void* cnt_ptr = nullptr;
    cudaGetSymbolAddress(&vox_ptr, g_vox);
    cudaGetSymbolAddress(&cnt_ptr, g_cnt);

    cudaMemsetAsync(vox_ptr, 0, (size_t)NB * R3 * NC * sizeof(float));
    cudaMemsetAsync(cnt_ptr, 0, (size_t)NB * R3 * sizeof(float));

    k_stats<<<16, 1024>>>(x1c, x2c);

    dim3 grid(NPTS / TILE, NB);
    k_voxelize<<<grid, 256>>>(x2f, x2c);

    k_finalize<<<(NB * R3 * 8) / 256, 256>>>();

    k_devox_concat<<<grid, 256>>>(x1f, x1c, out);
}

// round 3
// speedup vs baseline: 1.2529x; 1.1239x over previous
#include <cuda_runtime.h>
#include <cuda_fp16.h>
#include <cstdint>

#define NB 8
#define NC 64
#define NPTS 65536
#define RR 32
#define R3 32768
#define TILE 128          // voxelize tile
#define DT 64             // devox tile
#define INVN (1.0f / 65536.0f)

// ---------------- device scratch ----------------
__device__ __half g_voxh[(size_t)NB * R3 * NC];   // fp16 voxel sums -> averages (in place)
__device__ float  g_cnt [NB * R3];                // per-voxel point counts
__device__ float  g_stats[2 * NB * 4];            // [t][b]{sumx,sumy,sumz, maxsq}

// ---------------- stats pass 1: partial axis sums via atomics ----------------
__global__ void __launch_bounds__(256) k_sum(const float* __restrict__ c1,
                                             const float* __restrict__ c2) {
    int blk = blockIdx.x;           // 128 blocks: t(1) | b(3) | chunk(3)
    int t = blk >> 6, b = (blk >> 3) & 7, ch = blk & 7;
    const float* cb = (t ? c2 : c1) + (size_t)b * 3 * NPTS;
    const int CH = NPTS / 8;
    const float4* px = (const float4*)(cb + ch * CH);
    const float4* py = (const float4*)(cb + NPTS + ch * CH);
    const float4* pz = (const float4*)(cb + 2 * NPTS + ch * CH);

    float sx = 0.f, sy = 0.f, sz = 0.f;
    for (int i = threadIdx.x; i < CH / 4; i += 256) {
        float4 a = px[i]; sx += (a.x + a.y) + (a.z + a.w);
        float4 c = py[i]; sy += (c.x + c.y) + (c.z + c.w);
        float4 e = pz[i]; sz += (e.x + e.y) + (e.z + e.w);
    }
    #pragma unroll
    for (int o = 16; o > 0; o >>= 1) {
        sx += __shfl_down_sync(0xffffffffu, sx, o);
        sy += __shfl_down_sync(0xffffffffu, sy, o);
        sz += __shfl_down_sync(0xffffffffu, sz, o);
    }
    __shared__ float rs[8][3];
    if ((threadIdx.x & 31) == 0) {
        int w = threadIdx.x >> 5;
        rs[w][0] = sx; rs[w][1] = sy; rs[w][2] = sz;
    }
    __syncthreads();
    if (threadIdx.x < 3) {
        float s = 0.f;
        #pragma unroll
        for (int w = 0; w < 8; w++) s += rs[w][threadIdx.x];
        atomicAdd(&g_stats[(t * NB + b) * 4 + threadIdx.x], s);
    }
}

// ---------------- stats pass 2: max squared centered norm via atomicMax ----------------
__global__ void __launch_bounds__(256) k_maxsq(const float* __restrict__ c1,
                                               const float* __restrict__ c2) {
    int blk = blockIdx.x;
    int t = blk >> 6, b = (blk >> 3) & 7, ch = blk & 7;
    const float* cb = (t ? c2 : c1) + (size_t)b * 3 * NPTS;
    const float* st = &g_stats[(t * NB + b) * 4];
    float mx = st[0] * INVN, my = st[1] * INVN, mz = st[2] * INVN;

    const int CH = NPTS / 8;
    const float4* px = (const float4*)(cb + ch * CH);
    const float4* py = (const float4*)(cb + NPTS + ch * CH);
    const float4* pz = (const float4*)(cb + 2 * NPTS + ch * CH);

    float mm = 0.f;
    for (int i = threadIdx.x; i < CH / 4; i += 256) {
        float4 a = px[i], c = py[i], e = pz[i];
        float dx, dy, dz;
        dx = a.x - mx; dy = c.x - my; dz = e.x - mz; mm = fmaxf(mm, dx*dx + dy*dy + dz*dz);
        dx = a.y - mx; dy = c.y - my; dz = e.y - mz; mm = fmaxf(mm, dx*dx + dy*dy + dz*dz);
        dx = a.z - mx; dy = c.z - my; dz = e.z - mz; mm = fmaxf(mm, dx*dx + dy*dy + dz*dz);
        dx = a.w - mx; dy = c.w - my; dz = e.w - mz; mm = fmaxf(mm, dx*dx + dy*dy + dz*dz);
    }
    #pragma unroll
    for (int o = 16; o > 0; o >>= 1)
        mm = fmaxf(mm, __shfl_down_sync(0xffffffffu, mm, o));
    __shared__ float rs[8];
    if ((threadIdx.x & 31) == 0) rs[threadIdx.x >> 5] = mm;
    __syncthreads();
    if (threadIdx.x == 0) {
        float m = 0.f;
        #pragma unroll
        for (int w = 0; w < 8; w++) m = fmaxf(m, rs[w]);
        atomicMax((unsigned*)&g_stats[(t * NB + b) * 4 + 3], __float_as_uint(m));
    }
}

__device__ __forceinline__ float norm1(float v, float mean, float scale) {
    float x = ((v - mean) / scale + 0.5f) * (float)RR;
    return fminf(fmaxf(x, 0.0f), (float)(RR - 1));
}

// ---------------- voxelize x2 (fp16 vector red) + copy x1f -> out lower half ----------------
__global__ void __launch_bounds__(256) k_voxcopy(const float* __restrict__ feat,
                                                 const float* __restrict__ coords,
                                                 const float* __restrict__ x1f,
                                                 float* __restrict__ out) {
    int b  = blockIdx.y;
    int n0 = blockIdx.x * TILE;
    int tid = threadIdx.x;

    __shared__ float sfeat[TILE][68];
    __shared__ int   sidx[TILE];

    if (tid < TILE) {
        int n = n0 + tid;
        const float* cb = coords + (size_t)b * 3 * NPTS;
        const float* st = &g_stats[(1 * NB + b) * 4];
        float sc = 2.0f * sqrtf(st[3]);
        float nx = norm1(cb[n],            st[0] * INVN, sc);
        float ny = norm1(cb[NPTS + n],     st[1] * INVN, sc);
        float nz = norm1(cb[2 * NPTS + n], st[2] * INVN, sc);
        int vi = (((int)rintf(nx)) * RR + (int)rintf(ny)) * RR + (int)rintf(nz);
        sidx[tid] = vi;
        atomicAdd(&g_cnt[b * R3 + vi], 1.0f);
    }

    // coalesced feature load, transposed into smem (point-major)
    {
        int nl = tid & 127;
        for (int c = tid >> 7; c < NC; c += 2)
            sfeat[nl][c] = feat[((size_t)b * NC + c) * NPTS + n0 + nl];
    }

    // fused copy: x1_features -> out channels [0,64)
    {
        const float4* src = (const float4*)(x1f + (size_t)b * NC * NPTS);
        float4*       dst = (float4*)(out + (size_t)b * 2 * NC * NPTS);
        int g0 = n0 >> 2;
        for (int i = tid; i < NC * (TILE / 4); i += 256) {
            int c = i >> 5, g = i & 31;
            size_t off = (size_t)c * (NPTS / 4) + g0 + g;
            dst[off] = src[off];
        }
    }
    __syncthreads();

    // scatter: 8 fp16x8 vector reductions per point (128B/point)
    __half* vbase = g_voxh + (size_t)b * R3 * NC;
    for (int i = tid; i < TILE * 8; i += 256) {
        int nl = i >> 3;
        int c8 = i & 7;
        const float4* row = (const float4*)&sfeat[nl][c8 * 8];
        float4 a = row[0], c = row[1];
        __half2 p0 = __floats2half2_rn(a.x, a.y);
        __half2 p1 = __floats2half2_rn(a.z, a.w);
        __half2 p2 = __floats2half2_rn(c.x, c.y);
        __half2 p3 = __floats2half2_rn(c.z, c.w);
        __half* addr = vbase + (size_t)sidx[nl] * NC + c8 * 8;
        asm volatile("red.global.add.noftz.v4.f16x2 [%0], {%1,%2,%3,%4};"
                     :: "l"(addr),
                        "r"(*(unsigned*)&p0), "r"(*(unsigned*)&p1),
                        "r"(*(unsigned*)&p2), "r"(*(unsigned*)&p3) : "memory");
    }
}

// ---------------- finalize: in-place fp16 sums -> fp16 averages ----------------
__global__ void __launch_bounds__(256) k_finalize() {
    size_t i  = (size_t)blockIdx.x * 256 + threadIdx.x;
    size_t vg = i >> 3;
    int    c8 = (int)(i & 7);
    float inv = 1.0f / fmaxf(g_cnt[vg], 1.0f);
    uint4 v = *(uint4*)(g_voxh + vg * NC + c8 * 8);
    __half2* hp = (__half2*)&v;
    #pragma unroll
    for (int j = 0; j < 4; j++) {
        float2 f = __half22float2(hp[j]);
        hp[j] = __floats2half2_rn(f.x * inv, f.y * inv);
    }
    *(uint4*)(g_voxh + vg * NC + c8 * 8) = v;
}

// ---------------- devoxelize at nc_x1 -> out upper half ----------------
__global__ void __launch_bounds__(256, 6) k_devox(const float* __restrict__ x1c,
                                                  float* __restrict__ out) {
    int b  = blockIdx.y;
    int n0 = blockIdx.x * DT;
    int tid = threadIdx.x;

    __shared__ float sout[DT][65];
    __shared__ int   sidx[DT][8];
    __shared__ float sw[DT][8];

    if (tid < DT) {
        int n = n0 + tid;
        const float* cb = x1c + (size_t)b * 3 * NPTS;
        const float* st = &g_stats[(0 * NB + b) * 4];
        float sc = 2.0f * sqrtf(st[3]);
        float nx = norm1(cb[n],            st[0] * INVN, sc);
        float ny = norm1(cb[NPTS + n],     st[1] * INVN, sc);
        float nz = norm1(cb[2 * NPTS + n], st[2] * INVN, sc);

        float lx = floorf(nx), ly = floorf(ny), lz = floorf(nz);
        float dx = nx - lx,    dy = ny - ly,    dz = nz - lz;
        int ix = (int)lx, iy = (int)ly, iz = (int)lz;
        int hx = min(ix + 1, RR - 1), hy = min(iy + 1, RR - 1), hz = min(iz + 1, RR - 1);

        int   cx[2] = {ix, hx},       cy[2] = {iy, hy},       cz[2] = {iz, hz};
        float wx[2] = {1.f - dx, dx}, wy[2] = {1.f - dy, dy}, wz[2] = {1.f - dz, dz};

        #pragma unroll
        for (int k = 0; k < 8; k++) {
            int a = k >> 2, bb = (k >> 1) & 1, cc = k & 1;
            sidx[tid][k] = (cx[a] * RR + cy[bb]) * RR + cz[cc];
            sw[tid][k]   = wx[a] * wy[bb] * wz[cc];
        }
    }
    __syncthreads();

    // Phase C: fp16 gather (16 lanes x 8B cover one corner's 64 channels)
    {
        const uint2* vb = (const uint2*)(g_voxh + (size_t)b * R3 * NC);
        for (int i = tid; i < DT * 16; i += 256) {
            int nl = i >> 4;
            int c4 = i & 15;
            float a0 = 0.f, a1 = 0.f, a2 = 0.f, a3 = 0.f;
            #pragma unroll
            for (int k = 0; k < 8; k++) {
                int   idx = sidx[nl][k];
                float w   = sw[nl][k];
                uint2 v = vb[(size_t)idx * (NC / 4) + c4];
                float2 f0 = __half22float2(*(__half2*)&v.x);
                float2 f1 = __half22float2(*(__half2*)&v.y);
                a0 += w * f0.x; a1 += w * f0.y;
                a2 += w * f1.x; a3 += w * f1.y;
            }
            int c = c4 * 4;
            sout[nl][c + 0] = a0;
            sout[nl][c + 1] = a1;
            sout[nl][c + 2] = a2;
            sout[nl][c + 3] = a3;
        }
    }
    __syncthreads();

    // Phase D: transpose -> out channels [64,128), coalesced along N
    {
        float* dsto = out + ((size_t)b * 2 * NC + NC) * NPTS;
        for (int i = tid; i < NC * DT; i += 256) {
            int c = i >> 6, nl = i & 63;
            dsto[(size_t)c * NPTS + n0 + nl] = sout[nl][c];
        }
    }
}

// ---------------- launch ----------------
extern "C" void kernel_launch(void* const* d_in, const int* in_sizes, int n_in,
                              void* d_out, int out_size) {
    const float* fptr[2] = {nullptr, nullptr};
    const float* cptr[2] = {nullptr, nullptr};
    int fi = 0, ci = 0;
    for (int i = 0; i < 4; i++) {
        if (in_sizes[i] == NB * NC * NPTS) { if (fi < 2) fptr[fi++] = (const float*)d_in[i]; }
        else                               { if (ci < 2) cptr[ci++] = (const float*)d_in[i]; }
    }
    const float* x1f = fptr[0];
    const float* x2f = fptr[1];
    const float* x1c = cptr[0];
    const float* x2c = cptr[1];
    float* out = (float*)d_out;

    void *voxh_ptr = nullptr, *cnt_ptr = nullptr, *stats_ptr = nullptr;
    cudaGetSymbolAddress(&voxh_ptr, g_voxh);
    cudaGetSymbolAddress(&cnt_ptr,  g_cnt);
    cudaGetSymbolAddress(&stats_ptr, g_stats);

    cudaMemsetAsync(voxh_ptr, 0, (size_t)NB * R3 * NC * sizeof(__half));
    cudaMemsetAsync(cnt_ptr,  0, (size_t)NB * R3 * sizeof(float));
    cudaMemsetAsync(stats_ptr, 0, 2 * NB * 4 * sizeof(float));

    k_sum<<<128, 256>>>(x1c, x2c);
    k_maxsq<<<128, 256>>>(x1c, x2c);

    dim3 gv(NPTS / TILE, NB);
    k_voxcopy<<<gv, 256>>>(x2f, x2c, x1f, out);

    k_finalize<<<(NB * R3 * 8) / 256, 256>>>();

    dim3 gd(NPTS / DT, NB);
    k_devox<<<gd, 256>>>(x1c, out);
}